// round 12
// baseline (speedup 1.0000x reference)
#include <cuda_runtime.h>
#include <cstdint>

#define ZTOT    262144
#define THREADS 512
#define TILE_Z  128
#define NTILES  (ZTOT / TILE_Z)   // 2048
#define GRID    148

// ---- smem layout (bytes) ----
#define OFF_A    0
#define A_CHB    16384                     // per-channel A frags (64 z)
#define XPITCHB  1040                      // x stage row pitch (260 floats)
#define OFF_X0   65536
#define OFF_X1   (OFF_X0 + 66560)          // 132096
#define OFF_Y    (OFF_X1 + 66560)          // 198656
#define OFF_TPW  (OFF_Y + 2048)            // 200704
#define SMEM_BYTES (OFF_TPW + 1024)        // 201728
#define PITCHF   388                       // epilogue stage pitch (floats), 97 uint4

__device__ __forceinline__ uint32_t to_tf32(float f) {
    uint32_t u;
    asm("cvt.rna.tf32.f32 %0, %1;" : "=r"(u) : "f"(f));
    return u;
}

__device__ __forceinline__ void mma8(float* c, uint4 a, uint32_t b0, uint32_t b1) {
    asm("mma.sync.aligned.m16n8k8.row.col.f32.tf32.tf32.f32 "
        "{%0,%1,%2,%3}, {%4,%5,%6,%7}, {%8,%9}, {%0,%1,%2,%3};"
        : "+f"(c[0]), "+f"(c[1]), "+f"(c[2]), "+f"(c[3])
        : "r"(a.x), "r"(a.y), "r"(a.z), "r"(a.w), "r"(b0), "r"(b1));
}

__device__ __forceinline__ void cpasync16(uint32_t dst, const void* src) {
    asm volatile("cp.async.cg.shared.global [%0], [%1], 16;" :: "r"(dst), "l"(src));
}
#define CP_COMMIT() asm volatile("cp.async.commit_group;" ::: "memory")
#define CP_WAIT(n)  asm volatile("cp.async.wait_group %0;" :: "n"(n) : "memory")
#define BAR_SYNC(id)   asm volatile("bar.sync %0, 512;"   :: "r"(id) : "memory")
#define BAR_ARRIVE(id) asm volatile("bar.arrive %0, 512;" :: "r"(id) : "memory")

__global__ void __launch_bounds__(THREADS, 1)
tp_kernel(const float* __restrict__ x, const float* __restrict__ y,
          const float* __restrict__ tpw, const float* __restrict__ w0,
          const float* __restrict__ w1, float* __restrict__ out)
{
    extern __shared__ char smc[];
    float* smf = (float*)smc;
    const int tid  = threadIdx.x;
    const int warp = tid >> 5;
    const int lane = tid & 31;
    const int g    = lane >> 2;
    const int th4  = lane & 3;
    const uint32_t sb = (uint32_t)__cvta_generic_to_shared(smc);

    // ---- Phase-B roles + B fragments in registers (x0.125, tf32) ----
    const int ch = warp >> 2;              // warps 0-3: ch0 (consumer role)
    const int q  = warp & 3;
    const float* W = (ch == 0) ? w0 : w1;
    uint32_t bfr[8][4][2];
    #pragma unroll
    for (int ki = 0; ki < 8; ++ki)
        #pragma unroll
        for (int ni = 0; ni < 4; ++ni) {
            const int n  = q * 32 + ni * 8 + g;
            const int u0 = ki * 8 + th4;
            bfr[ki][ni][0] = to_tf32(W[u0 * 128 + n] * 0.125f);
            bfr[ki][ni][1] = to_tf32(W[(u0 + 4) * 128 + n] * 0.125f);
        }

    if (tid < 64) {
        smf[OFF_TPW/4 + tid]       = 0.7071067811865476f * tpw[tid];        // ca
        smf[OFF_TPW/4 + 64 + tid]  = 0.7071067811865476f * tpw[64 + tid];   // cb
        smf[OFF_TPW/4 + 128 + tid] = 0.7071067811865476f * tpw[128 + tid];  // cc
        smf[OFF_TPW/4 + 192 + tid] = 0.4082482904638631f * tpw[192 + tid];  // cd
    }

    // ---- Phase-A roles (64-z half) ----
    const int miL = warp >> 2;        // 0..3
    const int kb  = (warp & 3) * 2;   // ki = kb, kb+1
    const int r0  = miL * 16 + g;

    float* aArr = smf + OFF_A/4 + ch * (A_CHB/4) + lane * 4;

    auto load_half = [&](int t, int h, int b) {
        const float* xsrc = x + ((size_t)t * TILE_Z + h * 64) * 256;
        const uint32_t xb = sb + ((b == 0) ? OFF_X0 : OFF_X1);
        #pragma unroll
        for (int it = 0; it < 8; ++it) {
            const int idx = tid + it * THREADS;
            const int row = idx >> 6, c = idx & 63;
            cpasync16(xb + row * XPITCHB + c * 16, xsrc + row * 256 + c * 4);
        }
        if (tid < 64)
            cpasync16(sb + OFF_Y + b * 1024 + tid * 16,
                      y + ((size_t)t * TILE_Z + h * 64 + tid) * 4);
        CP_COMMIT();
    };

    int tile = blockIdx.x;
    int buf = 0;
    if (tile < NTILES) load_half(tile, 0, 0);
    // pre-arm the "stage free" barriers (consumer side)
    if (warp < 4) { BAR_ARRIVE(3); BAR_ARRIVE(4); }
    __syncthreads();

    for (; tile < NTILES; tile += GRID) {
        #pragma unroll 1
        for (int h = 0; h < 2; ++h) {
            // x(this half) arrival; also guarantees consumer finished all
            // copies of the previous half's stage (it only reaches this
            // barrier after its mi=3 copy) -> prefetch below is WAR-safe.
            CP_WAIT(0);
            __syncthreads();

            int nt = tile, nh = h + 1;
            if (nh == 2) { nt = tile + GRID; nh = 0; }
            if (nt < NTILES) load_half(nt, nh, buf ^ 1);

            const float* xs = smf + ((buf == 0) ? OFF_X0 : OFF_X1) / 4;
            const float4* ys = (const float4*)(smc + OFF_Y) + buf * 64;
            float* stg = smf + ((buf == 0) ? OFF_X0 : OFF_X1) / 4;  // reuse after A

            // ---- Phase A: mids -> A fragments, conflict-free (all warps) ----
            {
                const float4 yy0 = ys[r0];
                const float4 yy1 = ys[r0 + 8];
                #pragma unroll
                for (int kk = 0; kk < 2; ++kk) {
                    const int ki = kb + kk;
                    const int u  = ki * 8 + th4;
                    const float caA = smf[OFF_TPW/4 + u],       caB = smf[OFF_TPW/4 + u + 4];
                    const float cbA = smf[OFF_TPW/4 + 64 + u],  cbB = smf[OFF_TPW/4 + 68 + u];
                    const float ccA = smf[OFF_TPW/4 + 128 + u], ccB = smf[OFF_TPW/4 + 132 + u];
                    const float cdA = smf[OFF_TPW/4 + 192 + u], cdB = smf[OFF_TPW/4 + 196 + u];
                    uint4 q0, q1, q2, q3;
                    #pragma unroll
                    for (int i1 = 0; i1 < 2; ++i1) {
                        const float4 yy = i1 ? yy1 : yy0;
                        const float* xr = xs + (r0 + 8 * i1) * (XPITCHB/4);
                        const float x0A = xr[u], x0B = xr[u + 4];
                        const float aA = xr[64 + 3*u], bA = xr[65 + 3*u], cA = xr[66 + 3*u];
                        const float aB = xr[76 + 3*u], bB = xr[77 + 3*u], cB = xr[78 + 3*u];
                        const float dA  = fmaf(aA, yy.y, fmaf(bA, yy.z, cA * yy.w));
                        const float m0A = fmaf(caA * x0A, yy.x, cdA * dA);
                        const float qqA = cbA * x0A, rrA = ccA * yy.x;
                        const float dB  = fmaf(aB, yy.y, fmaf(bB, yy.z, cB * yy.w));
                        const float m0B = fmaf(caB * x0B, yy.x, cdB * dB);
                        const float qqB = cbB * x0B, rrB = ccB * yy.x;
                        const uint32_t v0A = to_tf32(m0A);
                        const uint32_t v1A = to_tf32(fmaf(qqA, yy.y, rrA * aA));
                        const uint32_t v2A = to_tf32(fmaf(qqA, yy.z, rrA * bA));
                        const uint32_t v3A = to_tf32(fmaf(qqA, yy.w, rrA * cA));
                        const uint32_t v0B = to_tf32(m0B);
                        const uint32_t v1B = to_tf32(fmaf(qqB, yy.y, rrB * aB));
                        const uint32_t v2B = to_tf32(fmaf(qqB, yy.z, rrB * bB));
                        const uint32_t v3B = to_tf32(fmaf(qqB, yy.w, rrB * cB));
                        if (i1 == 0) {
                            q0.x = v0A; q0.z = v0B;  q1.x = v1A; q1.z = v1B;
                            q2.x = v2A; q2.z = v2B;  q3.x = v3A; q3.z = v3B;
                        } else {
                            q0.y = v0A; q0.w = v0B;  q1.y = v1A; q1.w = v1B;
                            q2.y = v2A; q2.w = v2B;  q3.y = v3A; q3.w = v3B;
                        }
                    }
                    const int block = miL * 8 + ki;
                    char* ab = smc + OFF_A + block * 512 + lane * 16;
                    *(uint4*)(ab)               = q0;
                    *(uint4*)(ab + A_CHB)       = q1;
                    *(uint4*)(ab + 2 * A_CHB)   = q2;
                    *(uint4*)(ab + 3 * A_CHB)   = q3;
                }
            }
            __syncthreads();

            // ---- Phase B: producers (ch1-3) stage; consumers (ch0) copy ----
            const size_t zb = (size_t)tile * TILE_Z + h * 64;
            if (warp >= 4) {
                // ======== producer: MMA + stage (ping-pong S[mi&1]) ========
                #pragma unroll 1
                for (int mi = 0; mi < 4; ++mi) {
                    const int b = mi & 1;
                    float acc[4][4];
                    #pragma unroll
                    for (int ni = 0; ni < 4; ++ni)
                        #pragma unroll
                        for (int pp = 0; pp < 4; ++pp) acc[ni][pp] = 0.f;
                    #pragma unroll
                    for (int ki = 0; ki < 8; ++ki) {
                        const uint4 av = *(const uint4*)(aArr + (mi * 8 + ki) * 128);
                        #pragma unroll
                        for (int ni = 0; ni < 4; ++ni)
                            mma8(acc[ni], av, bfr[ki][ni][0], bfr[ki][ni][1]);
                    }
                    BAR_SYNC(3 + b);                 // wait: stage b free
                    float* sr = stg + b * (16 * PITCHF);
                    #pragma unroll
                    for (int ni = 0; ni < 4; ++ni) {
                        const int c0 = 3 * (q * 32 + ni * 8 + 2 * th4) + (ch - 1);
                        sr[g * PITCHF + c0]           = acc[ni][0];
                        sr[g * PITCHF + c0 + 3]       = acc[ni][1];
                        sr[(g + 8) * PITCHF + c0]     = acc[ni][2];
                        sr[(g + 8) * PITCHF + c0 + 3] = acc[ni][3];
                    }
                    __threadfence_block();
                    BAR_ARRIVE(1 + b);               // stage b ready
                }
            } else {
                // ======== consumer: own MMA + direct STG, then copy service =====
                #pragma unroll 1
                for (int mi = 0; mi < 4; ++mi) {
                    const int b = mi & 1;
                    float acc[4][4];
                    #pragma unroll
                    for (int ni = 0; ni < 4; ++ni)
                        #pragma unroll
                        for (int pp = 0; pp < 4; ++pp) acc[ni][pp] = 0.f;
                    #pragma unroll
                    for (int ki = 0; ki < 8; ++ki) {
                        const uint4 av = *(const uint4*)(aArr + (mi * 8 + ki) * 128);
                        #pragma unroll
                        for (int ni = 0; ni < 4; ++ni)
                            mma8(acc[ni], av, bfr[ki][ni][0], bfr[ki][ni][1]);
                    }
                    // direct sector-aligned STG into out[:,0:128]
                    {
                        float* ob = out + (zb + 16 * mi) * 512;
                        #pragma unroll
                        for (int ni = 0; ni < 4; ++ni) {
                            const int nc = q * 32 + ni * 8 + 2 * th4;
                            *(float2*)(ob + (size_t)g * 512 + nc) =
                                make_float2(acc[ni][0], acc[ni][1]);
                            *(float2*)(ob + (size_t)(g + 8) * 512 + nc) =
                                make_float2(acc[ni][2], acc[ni][3]);
                        }
                    }
                    BAR_SYNC(1 + b);                 // wait: stage b ready
                    // copy 16 rows x 384 floats -> out[:,128:512]
                    {
                        const uint4* st4 = (const uint4*)(stg + b * (16 * PITCHF));
                        float* ob = out + (zb + 16 * mi) * 512 + 128;
                        #pragma unroll
                        for (int it = 0; it < 12; ++it) {
                            const int idx = tid + it * 128;   // 0..1535
                            const int r = idx / 96, f = idx - r * 96;
                            *(uint4*)(ob + (size_t)r * 512 + f * 4) = st4[r * 97 + f];
                        }
                    }
                    BAR_ARRIVE(3 + b);               // stage b free
                }
            }
            buf ^= 1;
        }
    }
}

extern "C" void kernel_launch(void* const* d_in, const int* in_sizes, int n_in,
                              void* d_out, int out_size) {
    const float* x   = (const float*)d_in[0];
    const float* y   = (const float*)d_in[1];
    const float* tpw = (const float*)d_in[2];
    const float* w0  = (const float*)d_in[3];
    const float* w1  = (const float*)d_in[4];
    float* out = (float*)d_out;
    cudaFuncSetAttribute(tp_kernel, cudaFuncAttributeMaxDynamicSharedMemorySize,
                         SMEM_BYTES);
    tp_kernel<<<GRID, THREADS, SMEM_BYTES>>>(x, y, tpw, w0, w1, out);
}

// round 13
// speedup vs baseline: 1.2672x; 1.2672x over previous
#include <cuda_runtime.h>
#include <cstdint>

#define ZTOT    262144
#define THREADS 512
#define TILE_Z  128
#define NTILES  (ZTOT / TILE_Z)   // 2048
#define GRID    148

// ---- smem layout (bytes) ----
#define OFF_A    0
#define A_CHB    16384                     // per-channel A frags (64 z)
#define XPITCHB  1040                      // x stage row pitch (260 floats)
#define OFF_X0   65536
#define OFF_X1   (OFF_X0 + 66560)          // 132096
#define OFF_Y    (OFF_X1 + 66560)          // 198656
#define OFF_TPW  (OFF_Y + 2048)            // 200704
#define SMEM_BYTES (OFF_TPW + 1024)        // 201728
#define PITCHF   388                       // stage pitch (floats), 97 uint4
#define STAGEF   (16 * PITCHF)             // floats per 16-row stage

__device__ __forceinline__ uint32_t to_tf32(float f) {
    uint32_t u;
    asm("cvt.rna.tf32.f32 %0, %1;" : "=r"(u) : "f"(f));
    return u;
}

__device__ __forceinline__ void mma8(float* c, uint4 a, uint32_t b0, uint32_t b1) {
    asm("mma.sync.aligned.m16n8k8.row.col.f32.tf32.tf32.f32 "
        "{%0,%1,%2,%3}, {%4,%5,%6,%7}, {%8,%9}, {%0,%1,%2,%3};"
        : "+f"(c[0]), "+f"(c[1]), "+f"(c[2]), "+f"(c[3])
        : "r"(a.x), "r"(a.y), "r"(a.z), "r"(a.w), "r"(b0), "r"(b1));
}

__device__ __forceinline__ void cpasync16(uint32_t dst, const void* src) {
    asm volatile("cp.async.cg.shared.global [%0], [%1], 16;" :: "r"(dst), "l"(src));
}
#define CP_COMMIT() asm volatile("cp.async.commit_group;" ::: "memory")
#define CP_WAIT(n)  asm volatile("cp.async.wait_group %0;" :: "n"(n) : "memory")

__global__ void __launch_bounds__(THREADS, 1)
tp_kernel(const float* __restrict__ x, const float* __restrict__ y,
          const float* __restrict__ tpw, const float* __restrict__ w0,
          const float* __restrict__ w1, float* __restrict__ out)
{
    extern __shared__ char smc[];
    float* smf = (float*)smc;
    const int tid  = threadIdx.x;
    const int warp = tid >> 5;
    const int lane = tid & 31;
    const int g    = lane >> 2;
    const int th4  = lane & 3;
    const uint32_t sb = (uint32_t)__cvta_generic_to_shared(smc);

    // ---- Phase-B roles + B fragments in registers (x0.125, tf32) ----
    const int ch = warp >> 2;
    const int q  = warp & 3;
    const float* W = (ch == 0) ? w0 : w1;
    uint32_t bfr[8][4][2];
    #pragma unroll
    for (int ki = 0; ki < 8; ++ki)
        #pragma unroll
        for (int ni = 0; ni < 4; ++ni) {
            const int n  = q * 32 + ni * 8 + g;
            const int u0 = ki * 8 + th4;
            bfr[ki][ni][0] = to_tf32(W[u0 * 128 + n] * 0.125f);
            bfr[ki][ni][1] = to_tf32(W[(u0 + 4) * 128 + n] * 0.125f);
        }

    if (tid < 64) {
        smf[OFF_TPW/4 + tid]       = 0.7071067811865476f * tpw[tid];        // ca
        smf[OFF_TPW/4 + 64 + tid]  = 0.7071067811865476f * tpw[64 + tid];   // cb
        smf[OFF_TPW/4 + 128 + tid] = 0.7071067811865476f * tpw[128 + tid];  // cc
        smf[OFF_TPW/4 + 192 + tid] = 0.4082482904638631f * tpw[192 + tid];  // cd
    }

    // ---- Phase-A roles (64-z half) ----
    const int miL = warp >> 2;        // 0..3
    const int kb  = (warp & 3) * 2;   // ki = kb, kb+1
    const int r0  = miL * 16 + g;

    float* aArr = smf + OFF_A/4 + ch * (A_CHB/4) + lane * 4;

    auto load_half = [&](int t, int h, int b) {
        const float* xsrc = x + ((size_t)t * TILE_Z + h * 64) * 256;
        const uint32_t xb = sb + ((b == 0) ? OFF_X0 : OFF_X1);
        #pragma unroll
        for (int it = 0; it < 8; ++it) {
            const int idx = tid + it * THREADS;
            const int row = idx >> 6, c = idx & 63;
            cpasync16(xb + row * XPITCHB + c * 16, xsrc + row * 256 + c * 4);
        }
        if (tid < 64)
            cpasync16(sb + OFF_Y + b * 1024 + tid * 16,
                      y + ((size_t)t * TILE_Z + h * 64 + tid) * 4);
        CP_COMMIT();
    };

    int tile = blockIdx.x;
    int buf = 0;
    if (tile < NTILES) load_half(tile, 0, 0);
    __syncthreads();

    for (; tile < NTILES; tile += GRID) {
        #pragma unroll 1
        for (int h = 0; h < 2; ++h) {
            int nt = tile, nh = h + 1;
            if (nh == 2) { nt = tile + GRID; nh = 0; }
            const bool has_next = (nt < NTILES);
            if (has_next) load_half(nt, nh, buf ^ 1);
            if (has_next) { CP_WAIT(1); } else { CP_WAIT(0); }
            __syncthreads();

            const float* xs = smf + ((buf == 0) ? OFF_X0 : OFF_X1) / 4;
            const float4* ys = (const float4*)(smc + OFF_Y) + buf * 64;
            float* stg = smf + ((buf == 0) ? OFF_X0 : OFF_X1) / 4;  // reuse after A

            // ---- Phase A: mids -> A fragments, conflict-free ----
            {
                const float4 yy0 = ys[r0];
                const float4 yy1 = ys[r0 + 8];
                #pragma unroll
                for (int kk = 0; kk < 2; ++kk) {
                    const int ki = kb + kk;
                    const int u  = ki * 8 + th4;
                    const float caA = smf[OFF_TPW/4 + u],       caB = smf[OFF_TPW/4 + u + 4];
                    const float cbA = smf[OFF_TPW/4 + 64 + u],  cbB = smf[OFF_TPW/4 + 68 + u];
                    const float ccA = smf[OFF_TPW/4 + 128 + u], ccB = smf[OFF_TPW/4 + 132 + u];
                    const float cdA = smf[OFF_TPW/4 + 192 + u], cdB = smf[OFF_TPW/4 + 196 + u];
                    uint4 q0, q1, q2, q3;
                    #pragma unroll
                    for (int i1 = 0; i1 < 2; ++i1) {
                        const float4 yy = i1 ? yy1 : yy0;
                        const float* xr = xs + (r0 + 8 * i1) * (XPITCHB/4);
                        const float x0A = xr[u], x0B = xr[u + 4];
                        const float aA = xr[64 + 3*u], bA = xr[65 + 3*u], cA = xr[66 + 3*u];
                        const float aB = xr[76 + 3*u], bB = xr[77 + 3*u], cB = xr[78 + 3*u];
                        const float dA  = fmaf(aA, yy.y, fmaf(bA, yy.z, cA * yy.w));
                        const float m0A = fmaf(caA * x0A, yy.x, cdA * dA);
                        const float qqA = cbA * x0A, rrA = ccA * yy.x;
                        const float dB  = fmaf(aB, yy.y, fmaf(bB, yy.z, cB * yy.w));
                        const float m0B = fmaf(caB * x0B, yy.x, cdB * dB);
                        const float qqB = cbB * x0B, rrB = ccB * yy.x;
                        const uint32_t v0A = to_tf32(m0A);
                        const uint32_t v1A = to_tf32(fmaf(qqA, yy.y, rrA * aA));
                        const uint32_t v2A = to_tf32(fmaf(qqA, yy.z, rrA * bA));
                        const uint32_t v3A = to_tf32(fmaf(qqA, yy.w, rrA * cA));
                        const uint32_t v0B = to_tf32(m0B);
                        const uint32_t v1B = to_tf32(fmaf(qqB, yy.y, rrB * aB));
                        const uint32_t v2B = to_tf32(fmaf(qqB, yy.z, rrB * bB));
                        const uint32_t v3B = to_tf32(fmaf(qqB, yy.w, rrB * cB));
                        if (i1 == 0) {
                            q0.x = v0A; q0.z = v0B;  q1.x = v1A; q1.z = v1B;
                            q2.x = v2A; q2.z = v2B;  q3.x = v3A; q3.z = v3B;
                        } else {
                            q0.y = v0A; q0.w = v0B;  q1.y = v1A; q1.w = v1B;
                            q2.y = v2A; q2.w = v2B;  q3.y = v3A; q3.w = v3B;
                        }
                    }
                    const int block = miL * 8 + ki;
                    char* ab = smc + OFF_A + block * 512 + lane * 16;
                    *(uint4*)(ab)               = q0;
                    *(uint4*)(ab + A_CHB)       = q1;
                    *(uint4*)(ab + 2 * A_CHB)   = q2;
                    *(uint4*)(ab + 3 * A_CHB)   = q3;
                }
            }
            __syncthreads();

            // ---- Phase B: per-mi segments; copy of stage mi-1 overlaps MMA mi ----
            const size_t zb = (size_t)tile * TILE_Z + h * 64;
            #pragma unroll 1
            for (int mi = 0; mi < 4; ++mi) {
                float acc[4][4];
                #pragma unroll
                for (int ni = 0; ni < 4; ++ni)
                    #pragma unroll
                    for (int pp = 0; pp < 4; ++pp) acc[ni][pp] = 0.f;

                #pragma unroll
                for (int ki = 0; ki < 8; ++ki) {
                    const uint4 av = *(const uint4*)(aArr + (mi * 8 + ki) * 128);
                    #pragma unroll
                    for (int ni = 0; ni < 4; ++ni)
                        mma8(acc[ni], av, bfr[ki][ni][0], bfr[ki][ni][1]);
                }

                if (ch == 0) {
                    // direct sector-aligned STG into out[:,0:128]
                    float* ob = out + (zb + 16 * mi) * 512;
                    #pragma unroll
                    for (int ni = 0; ni < 4; ++ni) {
                        const int nc = q * 32 + ni * 8 + 2 * th4;
                        *(float2*)(ob + (size_t)g * 512 + nc) =
                            make_float2(acc[ni][0], acc[ni][1]);
                        *(float2*)(ob + (size_t)(g + 8) * 512 + nc) =
                            make_float2(acc[ni][2], acc[ni][3]);
                    }
                } else {
                    float* sr = stg + (mi & 1) * STAGEF;
                    #pragma unroll
                    for (int ni = 0; ni < 4; ++ni) {
                        const int c0 = 3 * (q * 32 + ni * 8 + 2 * th4) + (ch - 1);
                        sr[g * PITCHF + c0]           = acc[ni][0];
                        sr[g * PITCHF + c0 + 3]       = acc[ni][1];
                        sr[(g + 8) * PITCHF + c0]     = acc[ni][2];
                        sr[(g + 8) * PITCHF + c0 + 3] = acc[ni][3];
                    }
                }

                // overlapped copy of previous stage (all 512 threads)
                if (mi > 0) {
                    const uint4* st4 = (const uint4*)(stg + ((mi - 1) & 1) * STAGEF);
                    float* ob = out + (zb + 16 * (mi - 1)) * 512 + 128;
                    #pragma unroll
                    for (int it = 0; it < 3; ++it) {
                        const int idx = tid + it * THREADS;   // 0..1535
                        const int r = idx / 96, f = idx - r * 96;
                        *(uint4*)(ob + (size_t)r * 512 + f * 4) = st4[r * 97 + f];
                    }
                }
                __syncthreads();
            }
            // tail: copy stage of mi=3
            {
                const uint4* st4 = (const uint4*)(stg + STAGEF);
                float* ob = out + (zb + 48) * 512 + 128;
                #pragma unroll
                for (int it = 0; it < 3; ++it) {
                    const int idx = tid + it * THREADS;
                    const int r = idx / 96, f = idx - r * 96;
                    *(uint4*)(ob + (size_t)r * 512 + f * 4) = st4[r * 97 + f];
                }
            }
            __syncthreads();
            buf ^= 1;
        }
    }
}

extern "C" void kernel_launch(void* const* d_in, const int* in_sizes, int n_in,
                              void* d_out, int out_size) {
    const float* x   = (const float*)d_in[0];
    const float* y   = (const float*)d_in[1];
    const float* tpw = (const float*)d_in[2];
    const float* w0  = (const float*)d_in[3];
    const float* w1  = (const float*)d_in[4];
    float* out = (float*)d_out;
    cudaFuncSetAttribute(tp_kernel, cudaFuncAttributeMaxDynamicSharedMemorySize,
                         SMEM_BYTES);
    tp_kernel<<<GRID, THREADS, SMEM_BYTES>>>(x, y, tpw, w0, w1, out);
}